// round 16
// baseline (speedup 1.0000x reference)
#include <cuda_runtime.h>
#include <cuda_fp16.h>
#include <math.h>
#include <stdint.h>

#define Bn 8
#define Nn 10000
#define Hh 64
#define Ll 4
#define Rr 3
#define Ee 200000
#define FPn 2048
#define ROWS (Nn*Bn)            /* 80000 rows; row m = node*8 + b */
#define LN_EPS 1e-3f
#define FSEG 64                 /* hist/fill blocks per relation */
#define FCHUNK (Ee/FSEG)        /* 3125 */
#define FILLB (Rr*FSEG)         /* 192 */
#define GCH 128

#define GDC_WAIT() asm volatile("griddepcontrol.wait;" ::: "memory")
#define GDC_LAUNCH() asm volatile("griddepcontrol.launch_dependents;")

// ---------------- device scratch ----------------
__device__ __half g_xh[ROWS*Hh];            // x (fp16) — single state buffer
__device__ __half g_aggh[Rr*ROWS*Hh];       // per-relation aggregation (fp16)
__device__ uint2  g_bfrag[Ll*16*8*32];      // B in exact mma-fragment order
__device__ float  g_film[Bn*2*Hh];
__device__ int    g_hist[Rr*Nn];            // degree hist (re-zeroed by scan)
__device__ int    g_rowptr[Rr*(Nn+1)];
__device__ int    g_cnt[Rr*Nn];             // atomic fill cursors
__device__ int2   g_epk[Rr*Ee];             // CSR packed (src, half2(w,w))

// ---------------- pre-kernel: hist(192, global atomics) + film(8) + prep_b(16)
__global__ __launch_bounds__(1024)
void pre_kernel(const int* __restrict__ ei,
                const float* __restrict__ fp,
                const float* __restrict__ W1, const float* __restrict__ b1,
                const float* __restrict__ W2, const float* __restrict__ b2,
                const float* __restrict__ Wself, const float* __restrict__ Wrel)
{
    __shared__ float part[1024];
    __shared__ float hid[64];
    int bk = blockIdx.x, t = threadIdx.x;

    if (bk < FILLB) {
        int r = bk / FSEG, seg = bk % FSEG;
        const int* dstp = ei + (r*2 + 1)*Ee + seg*FCHUNK;
        for (int e = t; e < FCHUNK; e += 1024)
            atomicAdd(&g_hist[r*Nn + dstp[e]], 1);
    } else if (bk < FILLB + Bn) {
        int b = bk - FILLB;
        int h = t >> 4, kc = t & 15;
        const float* fpb = fp + b*FPn;
        float a0 = 0.f, a1 = 0.f;
        int k0 = kc*128;
        for (int k = k0; k < k0 + 128; k += 2) {
            a0 = fmaf(fpb[k],   W1[k*Hh + h],     a0);
            a1 = fmaf(fpb[k+1], W1[(k+1)*Hh + h], a1);
        }
        part[t] = a0 + a1;
        __syncthreads();
        if (t < 64) {
            float a = b1[t];
            #pragma unroll
            for (int i = 0; i < 16; i++) a += part[t*16 + i];
            hid[t] = fmaxf(a, 0.f);
        }
        __syncthreads();
        if (t < 128) {
            int j = t;
            float a = b2[j];
            #pragma unroll
            for (int k = 0; k < Hh; k++) a += hid[k] * W2[k*128 + j];
            if (j < 64) g_film[b*128 + j] = 1.f + tanhf(a);
            else        g_film[b*128 + j] = a;
        }
    } else {
        int idx = (bk - FILLB - Bn)*1024 + t;
        if (idx < Ll*16*8*32) {
            int l    = idx >> 12;
            int kt   = (idx >> 8) & 15;
            int nt   = (idx >> 5) & 7;
            int lane = idx & 31;
            int s  = kt >> 2;
            int kb = (kt & 3)*16 + (lane & 3)*2;
            int n  = nt*8 + (lane >> 2);
            const float* W = (s == 0) ? (Wself + l*4096) : (Wrel + (l*Rr + s-1)*4096);
            __half2 lo = __floats2half2_rn(W[kb*64 + n],     W[(kb+1)*64 + n]);
            __half2 hi = __floats2half2_rn(W[(kb+8)*64 + n], W[(kb+9)*64 + n]);
            uint2 u;
            u.x = *(unsigned*)&lo;
            u.y = *(unsigned*)&hi;
            g_bfrag[idx] = u;
        }
    }
    GDC_LAUNCH();
}

// ---------------- scan: rowptr + cursors; re-zeros g_hist -------------------
__global__ __launch_bounds__(1024)
void scan_kernel()   // grid = Rr x 1024
{
    __shared__ int wsum[32];
    int r = blockIdx.x, t = threadIdx.x;
    int lane = t & 31, warp = t >> 5;
    GDC_WAIT();                     // needs g_hist from pre
    int carry = 0;
    if (t == 0) g_rowptr[r*(Nn+1)] = 0;
    for (int base = 0; base < Nn; base += 1024) {
        int idx = base + t;
        int v = (idx < Nn) ? g_hist[r*Nn + idx] : 0;
        int s = v;
        #pragma unroll
        for (int off = 1; off < 32; off <<= 1) {
            int nbr = __shfl_up_sync(0xffffffffu, s, off);
            if (lane >= off) s += nbr;
        }
        if (lane == 31) wsum[warp] = s;
        __syncthreads();
        if (warp == 0) {
            int w = wsum[lane];
            #pragma unroll
            for (int off = 1; off < 32; off <<= 1) {
                int nbr = __shfl_up_sync(0xffffffffu, w, off);
                if (lane >= off) w += nbr;
            }
            wsum[lane] = w;
        }
        __syncthreads();
        int tot = carry + (warp ? wsum[warp-1] : 0) + s;
        if (idx < Nn) {
            g_rowptr[r*(Nn+1) + idx + 1] = tot;
            g_cnt[r*Nn + idx]  = tot - v;
            g_hist[r*Nn + idx] = 0;
        }
        carry += wsum[31];
        __syncthreads();
    }
    GDC_LAUNCH();
}

// ---------------- fused fill(192) + init(2500) ------------------------------
// fill blocks wait on scan (cursors); init blocks depend only on pre -> NO wait,
// they run fully overlapped with the 3-block scan.
__global__ __launch_bounds__(256)
void fillinit_kernel(const int* __restrict__ ei, const float* __restrict__ ew,
                     const float* __restrict__ ctl, const float* __restrict__ drug,
                     const float* __restrict__ W_se, const float* __restrict__ b_se,
                     const float* __restrict__ cell_emb, const int* __restrict__ cell_idx)
{
    int bk = blockIdx.x, t = threadIdx.x;
    if (bk < FILLB) {
        GDC_WAIT();                 // needs g_cnt cursors from scan
        int r = bk / FSEG, seg = bk % FSEG;
        const int* dstp = ei + (r*2 + 1)*Ee + seg*FCHUNK;
        const int* srcp = ei + (r*2 + 0)*Ee + seg*FCHUNK;
        const float* wp = ew + r*Ee + seg*FCHUNK;
        for (int e = t; e < FCHUNK; e += 256) {
            int dst = dstp[e];
            int pos = atomicAdd(&g_cnt[r*Nn + dst], 1);
            float wv = wp[e];
            __half2 wh = __floats2half2_rn(wv, wv);
            g_epk[r*Ee + pos] = make_int2(srcp[e], *(int*)&wh);
        }
        GDC_LAUNCH();
        return;
    }
    // ---- init x: reads only g_film (transitively complete) + inputs ----
    __shared__ float sp[1664];
    for (int i = t; i < 1664; i += 256) {
        float v;
        if (i < 64)        v = W_se[i];
        else if (i < 128)  v = b_se[i - 64];
        else if (i < 640) {
            int j = i - 128, b = j >> 6, h = j & 63;
            v = cell_emb[cell_idx[b]*Hh + h];
        } else if (i < 1152) {
            int j = i - 640, b = j >> 6, h = j & 63;
            v = g_film[b*128 + h];
        } else {
            int j = i - 1152, b = j >> 6, h = j & 63;
            v = g_film[b*128 + 64 + h];
        }
        sp[i] = v;
    }
    __syncthreads();

    int i = (bk - FILLB)*256 + t;
    if (i < ROWS*8) {
        int q = i & 7;
        int m = i >> 3;
        int b = m & 7;
        int n = m >> 3;
        float v1 = ctl[b*Nn + n], v2 = drug[b*Nn + n];
        const float4* w4  = (const float4*)&sp[q*8];
        const float4* bb4 = (const float4*)&sp[64 + q*8];
        const float4* ce4 = (const float4*)&sp[128 + b*64 + q*8];
        const float4* g4  = (const float4*)&sp[640 + b*64 + q*8];
        const float4* be4 = (const float4*)&sp[1152 + b*64 + q*8];
        uint4 outv;
        unsigned* op = (unsigned*)&outv;
        #pragma unroll
        for (int p = 0; p < 2; p++) {
            float4 w = w4[p], bb = bb4[p], ce = ce4[p], gg = g4[p], be = be4[p];
            float o[4];
            o[0] = fmaf(fmaxf(fmaf(v1, w.x, bb.x), 0.f) + fmaxf(fmaf(v2, w.x, bb.x), 0.f) + ce.x, gg.x, be.x);
            o[1] = fmaf(fmaxf(fmaf(v1, w.y, bb.y), 0.f) + fmaxf(fmaf(v2, w.y, bb.y), 0.f) + ce.y, gg.y, be.y);
            o[2] = fmaf(fmaxf(fmaf(v1, w.z, bb.z), 0.f) + fmaxf(fmaf(v2, w.z, bb.z), 0.f) + ce.z, gg.z, be.z);
            o[3] = fmaf(fmaxf(fmaf(v1, w.w, bb.w), 0.f) + fmaxf(fmaf(v2, w.w, bb.w), 0.f) + ce.w, gg.w, be.w);
            __half2 h0 = __floats2half2_rn(o[0], o[1]);
            __half2 h1 = __floats2half2_rn(o[2], o[3]);
            op[p*2]   = *(unsigned*)&h0;
            op[p*2+1] = *(unsigned*)&h1;
        }
        ((uint4*)g_xh)[i] = outv;
    }
    GDC_LAUNCH();
}

// ---------------- gather: HFMA2 8-edge windows, fp32 flush ------------------
__device__ __forceinline__ void hacc4(__half2* a, uint4 v, __half2 w2)
{
    a[0] = __hfma2(*(__half2*)&v.x, w2, a[0]);
    a[1] = __hfma2(*(__half2*)&v.y, w2, a[1]);
    a[2] = __hfma2(*(__half2*)&v.z, w2, a[2]);
    a[3] = __hfma2(*(__half2*)&v.w, w2, a[3]);
}
__device__ __forceinline__ void hflush(float* f, __half2* a, __half2 hz)
{
    #pragma unroll
    for (int q = 0; q < 4; q++) {
        float2 x = __half22float2(a[q]);
        f[2*q]   += x.x;
        f[2*q+1] += x.y;
        a[q] = hz;
    }
}

__global__ __launch_bounds__(64)
void gather_kernel()  // grid (Nn, Rr) x 64
{
    __shared__ int2 sM[GCH];
    int dst = blockIdx.x, r = blockIdx.y;
    int t = threadIdx.x;                       // owns 8 halfs of the 512-half row
    // rowptr comes from scan (>=2 kernels back; transitively complete) -> pre-wait
    int start = g_rowptr[r*(Nn+1) + dst];
    int end   = g_rowptr[r*(Nn+1) + dst + 1];
    GDC_WAIT();                                // x / meta from immediate predecessor
    const uint4* __restrict__ xq = (const uint4*)g_xh;   // 64 uint4 per node row
    const int2* __restrict__ ep = g_epk + r*Ee;
    const __half2 hz = __float2half2_rn(0.f);
    float accf[8] = {0.f, 0.f, 0.f, 0.f, 0.f, 0.f, 0.f, 0.f};

    for (int base = start; base < end; base += GCH) {
        int n = min(GCH, end - base);
        if (t < n)       sM[t]      = ep[base + t];
        if (t + 64 < n)  sM[t + 64] = ep[base + t + 64];
        __syncthreads();
        int j = 0;
        for (; j + 8 <= n; j += 8) {
            __half2 a[4] = {hz, hz, hz, hz};
            int2 m0 = sM[j],   m1 = sM[j+1], m2 = sM[j+2], m3 = sM[j+3];
            int2 m4 = sM[j+4], m5 = sM[j+5], m6 = sM[j+6], m7 = sM[j+7];
            uint4 v0 = xq[m0.x*64 + t];
            uint4 v1 = xq[m1.x*64 + t];
            uint4 v2 = xq[m2.x*64 + t];
            uint4 v3 = xq[m3.x*64 + t];
            uint4 v4 = xq[m4.x*64 + t];
            uint4 v5 = xq[m5.x*64 + t];
            uint4 v6 = xq[m6.x*64 + t];
            uint4 v7 = xq[m7.x*64 + t];
            hacc4(a, v0, *(__half2*)&m0.y);
            hacc4(a, v1, *(__half2*)&m1.y);
            hacc4(a, v2, *(__half2*)&m2.y);
            hacc4(a, v3, *(__half2*)&m3.y);
            hacc4(a, v4, *(__half2*)&m4.y);
            hacc4(a, v5, *(__half2*)&m5.y);
            hacc4(a, v6, *(__half2*)&m6.y);
            hacc4(a, v7, *(__half2*)&m7.y);
            hflush(accf, a, hz);
        }
        if (j < n) {
            __half2 a[4] = {hz, hz, hz, hz};
            for (; j < n; j++) {
                int2 m0 = sM[j];
                uint4 v0 = xq[m0.x*64 + t];
                hacc4(a, v0, *(__half2*)&m0.y);
            }
            hflush(accf, a, hz);
        }
        __syncthreads();
    }

    uint4 hw;
    unsigned* hp = (unsigned*)&hw;
    #pragma unroll
    for (int q = 0; q < 4; q++) {
        __half2 h = __floats2half2_rn(accf[2*q], accf[2*q+1]);
        hp[q] = *(unsigned*)&h;
    }
    ((uint4*)(g_aggh + r*(ROWS*Hh) + dst*512))[t] = hw;
    GDC_LAUNCH();
}

// ---------------- HMMA GEMM (smem-staged A) + LN + ReLU (+ fused out) -------
__global__ __launch_bounds__(256)
void gemm_mma_kernel(const float* __restrict__ ln_g, const float* __restrict__ ln_b,
                     const float* __restrict__ W_out, const float* __restrict__ b_out,
                     float* __restrict__ out, int layer, int final_layer)
{
    __shared__ __half sA[128][72];
    __shared__ uint2  sBs[4*8*32];
    __shared__ float  sLN[194];

    int tid = threadIdx.x;
    int wid = tid >> 5, lane = tid & 31;
    int qr = lane >> 2, qc = lane & 3;

    // LN/out params are kernel inputs -> stage before the dependency wait
    if (tid < 64)        sLN[tid] = ln_g[layer*64 + tid];
    else if (tid < 128)  sLN[tid] = ln_b[layer*64 + tid - 64];
    else if (tid < 192)  sLN[tid] = W_out[tid - 128];
    else if (tid == 192) sLN[192] = b_out[0];
    GDC_WAIT();                                // agg/x from gather

    int m0 = blockIdx.x*128;
    int rl = wid*16 + qr;

    float c[8][4];
    #pragma unroll
    for (int nt = 0; nt < 8; nt++)
        #pragma unroll
        for (int i = 0; i < 4; i++) c[nt][i] = 0.f;

    for (int s = 0; s < 4; s++) {
        const uint4* Asrc = (const uint4*)(((s == 0) ? g_xh
                                : (g_aggh + (s-1)*(ROWS*Hh))) + m0*64);
        #pragma unroll
        for (int i = tid; i < 1024; i += 256) {
            int row = i >> 3, cq = i & 7;
            *(uint4*)&sA[row][cq*8] = Asrc[i];
        }
        const uint4* bsrc = (const uint4*)(g_bfrag + layer*4096 + s*1024);
        #pragma unroll
        for (int i = tid; i < 512; i += 256) ((uint4*)sBs)[i] = bsrc[i];
        __syncthreads();

        #pragma unroll
        for (int kti = 0; kti < 4; kti++) {
            int kh = kti*16 + qc*2;
            uint32_t a0 = *(const uint32_t*)&sA[rl][kh];
            uint32_t a1 = *(const uint32_t*)&sA[rl + 8][kh];
            uint32_t a2 = *(const uint32_t*)&sA[rl][kh + 8];
            uint32_t a3 = *(const uint32_t*)&sA[rl + 8][kh + 8];
            #pragma unroll
            for (int nt = 0; nt < 8; nt++) {
                uint2 b = sBs[(kti*8 + nt)*32 + lane];
                asm volatile(
                    "mma.sync.aligned.m16n8k16.row.col.f32.f16.f16.f32 "
                    "{%0,%1,%2,%3}, {%4,%5,%6,%7}, {%8,%9}, {%0,%1,%2,%3};"
                    : "+f"(c[nt][0]), "+f"(c[nt][1]), "+f"(c[nt][2]), "+f"(c[nt][3])
                    : "r"(a0), "r"(a1), "r"(a2), "r"(a3), "r"(b.x), "r"(b.y));
            }
        }
        __syncthreads();
    }

    #pragma unroll
    for (int h = 0; h < 2; h++) {
        int row = m0 + rl + h*8;
        float sum = 0.f, sq = 0.f;
        #pragma unroll
        for (int nt = 0; nt < 8; nt++) {
            float v0 = c[nt][2*h], v1 = c[nt][2*h + 1];
            sum += v0 + v1;
            sq   = fmaf(v0, v0, fmaf(v1, v1, sq));
        }
        sum += __shfl_xor_sync(0xffffffffu, sum, 1);
        sq  += __shfl_xor_sync(0xffffffffu, sq, 1);
        sum += __shfl_xor_sync(0xffffffffu, sum, 2);
        sq  += __shfl_xor_sync(0xffffffffu, sq, 2);
        float mu  = sum * (1.f/64.f);
        float var = sq  * (1.f/64.f) - mu*mu;
        float inv = rsqrtf(var + LN_EPS);
        if (!final_layer) {
            #pragma unroll
            for (int nt = 0; nt < 8; nt++) {
                int col = nt*8 + qc*2;
                float o0 = fmaxf(fmaf((c[nt][2*h]  -mu)*inv, sLN[col],   sLN[64+col]),   0.f);
                float o1 = fmaxf(fmaf((c[nt][2*h+1]-mu)*inv, sLN[col+1], sLN[64+col+1]), 0.f);
                __half2 hv = __floats2half2_rn(o0, o1);
                *(unsigned*)(g_xh + row*64 + col) = *(unsigned*)&hv;
            }
        } else {
            float dot = 0.f;
            #pragma unroll
            for (int nt = 0; nt < 8; nt++) {
                int col = nt*8 + qc*2;
                float o0 = fmaxf(fmaf((c[nt][2*h]  -mu)*inv, sLN[col],   sLN[64+col]),   0.f);
                float o1 = fmaxf(fmaf((c[nt][2*h+1]-mu)*inv, sLN[col+1], sLN[64+col+1]), 0.f);
                dot = fmaf(o0, sLN[128+col], fmaf(o1, sLN[128+col+1], dot));
            }
            dot += __shfl_xor_sync(0xffffffffu, dot, 1);
            dot += __shfl_xor_sync(0xffffffffu, dot, 2);
            if (qc == 0) {
                int b = row & 7, n = row >> 3;
                out[b*Nn + n] = dot + sLN[192];
            }
        }
    }
    GDC_LAUNCH();
}

// ---------------- PDL launch helper ----------------
static void launch_pdl(const void* fn, dim3 grid, dim3 block, void** args)
{
    cudaLaunchConfig_t cfg = {};
    cfg.gridDim = grid;
    cfg.blockDim = block;
    cfg.dynamicSmemBytes = 0;
    cfg.stream = 0;
    cudaLaunchAttribute at[1];
    at[0].id = cudaLaunchAttributeProgrammaticStreamSerialization;
    at[0].val.programmaticStreamSerializationAllowed = 1;
    cfg.attrs = at;
    cfg.numAttrs = 1;
    cudaLaunchKernelExC(&cfg, fn, args);
}

// ---------------- launch ----------------
extern "C" void kernel_launch(void* const* d_in, const int* in_sizes, int n_in,
                              void* d_out, int out_size)
{
    const float* ctl      = (const float*)d_in[0];
    const float* drug     = (const float*)d_in[1];
    const float* fp       = (const float*)d_in[2];
    const float* ew       = (const float*)d_in[3];
    const int*   cell_idx = (const int*)  d_in[4];
    const int*   ei       = (const int*)  d_in[5];
    const float* W_se     = (const float*)d_in[6];
    const float* b_se     = (const float*)d_in[7];
    const float* cell_emb = (const float*)d_in[8];
    const float* W_f1     = (const float*)d_in[9];
    const float* b_f1     = (const float*)d_in[10];
    const float* W_f2     = (const float*)d_in[11];
    const float* b_f2     = (const float*)d_in[12];
    const float* Wself    = (const float*)d_in[13];
    const float* Wrel     = (const float*)d_in[14];
    const float* ln_g     = (const float*)d_in[15];
    const float* ln_b     = (const float*)d_in[16];
    const float* W_out    = (const float*)d_in[17];
    const float* b_out    = (const float*)d_in[18];
    float* out = (float*)d_out;

    int npre = FILLB + Bn + (Ll*16*8*32 + 1023)/1024;   // 216
    {
        void* a[] = {(void*)&ei, (void*)&fp, (void*)&W_f1, (void*)&b_f1,
                     (void*)&W_f2, (void*)&b_f2, (void*)&Wself, (void*)&Wrel};
        launch_pdl((const void*)pre_kernel, dim3(npre), dim3(1024), a);      // 1
    }
    {
        void* a[] = {nullptr};
        launch_pdl((const void*)scan_kernel, dim3(Rr), dim3(1024), a);       // 2
    }
    {
        void* a[] = {(void*)&ei, (void*)&ew, (void*)&ctl, (void*)&drug,
                     (void*)&W_se, (void*)&b_se, (void*)&cell_emb, (void*)&cell_idx};
        launch_pdl((const void*)fillinit_kernel,
                   dim3(FILLB + (ROWS*8 + 255)/256), dim3(256), a);          // 3
    }

    int layers[Ll]  = {0, 1, 2, 3};
    int finals[Ll]  = {0, 0, 0, 1};
    for (int l = 0; l < Ll; l++) {
        {
            void* a[] = {nullptr};
            launch_pdl((const void*)gather_kernel, dim3(Nn, Rr), dim3(64), a);
        }
        {
            void* a[] = {(void*)&ln_g, (void*)&ln_b, (void*)&W_out, (void*)&b_out,
                         (void*)&out, (void*)&layers[l], (void*)&finals[l]};
            launch_pdl((const void*)gemm_mma_kernel, dim3(ROWS/128), dim3(256), a);
        }
    }
}

// round 17
// speedup vs baseline: 1.0047x; 1.0047x over previous
#include <cuda_runtime.h>
#include <cuda_fp16.h>
#include <math.h>
#include <stdint.h>

#define Bn 8
#define Nn 10000
#define Hh 64
#define Ll 4
#define Rr 3
#define Ee 200000
#define FPn 2048
#define ROWS (Nn*Bn)            /* 80000 rows; row m = node*8 + b */
#define LN_EPS 1e-3f
#define FSEG 64                 /* hist/fill blocks per relation */
#define FCHUNK (Ee/FSEG)        /* 3125 */
#define FILLB (Rr*FSEG)         /* 192 */
#define GCH 128

#define GDC_WAIT() asm volatile("griddepcontrol.wait;" ::: "memory")
#define GDC_LAUNCH() asm volatile("griddepcontrol.launch_dependents;")

// ---------------- device scratch ----------------
__device__ __half g_xh[ROWS*Hh];            // x (fp16) — single state buffer
__device__ __half g_aggh[Rr*ROWS*Hh];       // per-relation aggregation (fp16)
__device__ uint2  g_bfrag[Ll*16*8*32];      // B in exact mma-fragment order
__device__ float  g_film[Bn*2*Hh];
__device__ int    g_hist[Rr*Nn];            // degree hist (re-zeroed by scan)
__device__ int    g_rowptr[Rr*(Nn+1)];
__device__ int    g_cnt[Rr*Nn];             // atomic fill cursors
__device__ int2   g_epk[Rr*Ee];             // CSR packed (src, half2(w,w))

// ---------------- pre-kernel: hist(192, global atomics) + film(8) + prep_b(16)
__global__ __launch_bounds__(1024)
void pre_kernel(const int* __restrict__ ei,
                const float* __restrict__ fp,
                const float* __restrict__ W1, const float* __restrict__ b1,
                const float* __restrict__ W2, const float* __restrict__ b2,
                const float* __restrict__ Wself, const float* __restrict__ Wrel)
{
    __shared__ float part[1024];
    __shared__ float hid[64];
    int bk = blockIdx.x, t = threadIdx.x;

    if (bk < FILLB) {
        int r = bk / FSEG, seg = bk % FSEG;
        const int* dstp = ei + (r*2 + 1)*Ee + seg*FCHUNK;
        for (int e = t; e < FCHUNK; e += 1024)
            atomicAdd(&g_hist[r*Nn + dstp[e]], 1);
    } else if (bk < FILLB + Bn) {
        int b = bk - FILLB;
        int h = t >> 4, kc = t & 15;
        const float* fpb = fp + b*FPn;
        float a0 = 0.f, a1 = 0.f;
        int k0 = kc*128;
        for (int k = k0; k < k0 + 128; k += 2) {
            a0 = fmaf(fpb[k],   W1[k*Hh + h],     a0);
            a1 = fmaf(fpb[k+1], W1[(k+1)*Hh + h], a1);
        }
        part[t] = a0 + a1;
        __syncthreads();
        if (t < 64) {
            float a = b1[t];
            #pragma unroll
            for (int i = 0; i < 16; i++) a += part[t*16 + i];
            hid[t] = fmaxf(a, 0.f);
        }
        __syncthreads();
        if (t < 128) {
            int j = t;
            float a = b2[j];
            #pragma unroll
            for (int k = 0; k < Hh; k++) a += hid[k] * W2[k*128 + j];
            if (j < 64) g_film[b*128 + j] = 1.f + tanhf(a);
            else        g_film[b*128 + j] = a;
        }
    } else {
        int idx = (bk - FILLB - Bn)*1024 + t;
        if (idx < Ll*16*8*32) {
            int l    = idx >> 12;
            int kt   = (idx >> 8) & 15;
            int nt   = (idx >> 5) & 7;
            int lane = idx & 31;
            int s  = kt >> 2;
            int kb = (kt & 3)*16 + (lane & 3)*2;
            int n  = nt*8 + (lane >> 2);
            const float* W = (s == 0) ? (Wself + l*4096) : (Wrel + (l*Rr + s-1)*4096);
            __half2 lo = __floats2half2_rn(W[kb*64 + n],     W[(kb+1)*64 + n]);
            __half2 hi = __floats2half2_rn(W[(kb+8)*64 + n], W[(kb+9)*64 + n]);
            uint2 u;
            u.x = *(unsigned*)&lo;
            u.y = *(unsigned*)&hi;
            g_bfrag[idx] = u;
        }
    }
    GDC_LAUNCH();
}

// ---------------- scan: rowptr + cursors; re-zeros g_hist -------------------
__global__ __launch_bounds__(1024)
void scan_kernel()   // grid = Rr x 1024
{
    __shared__ int wsum[32];
    int r = blockIdx.x, t = threadIdx.x;
    int lane = t & 31, warp = t >> 5;
    GDC_WAIT();                     // needs g_hist from pre
    int carry = 0;
    if (t == 0) g_rowptr[r*(Nn+1)] = 0;
    for (int base = 0; base < Nn; base += 1024) {
        int idx = base + t;
        int v = (idx < Nn) ? g_hist[r*Nn + idx] : 0;
        int s = v;
        #pragma unroll
        for (int off = 1; off < 32; off <<= 1) {
            int nbr = __shfl_up_sync(0xffffffffu, s, off);
            if (lane >= off) s += nbr;
        }
        if (lane == 31) wsum[warp] = s;
        __syncthreads();
        if (warp == 0) {
            int w = wsum[lane];
            #pragma unroll
            for (int off = 1; off < 32; off <<= 1) {
                int nbr = __shfl_up_sync(0xffffffffu, w, off);
                if (lane >= off) w += nbr;
            }
            wsum[lane] = w;
        }
        __syncthreads();
        int tot = carry + (warp ? wsum[warp-1] : 0) + s;
        if (idx < Nn) {
            g_rowptr[r*(Nn+1) + idx + 1] = tot;
            g_cnt[r*Nn + idx]  = tot - v;
            g_hist[r*Nn + idx] = 0;
        }
        carry += wsum[31];
        __syncthreads();
    }
    GDC_LAUNCH();
}

// ---------------- fused fill(192) + init(2500) ------------------------------
__global__ __launch_bounds__(256)
void fillinit_kernel(const int* __restrict__ ei, const float* __restrict__ ew,
                     const float* __restrict__ ctl, const float* __restrict__ drug,
                     const float* __restrict__ W_se, const float* __restrict__ b_se,
                     const float* __restrict__ cell_emb, const int* __restrict__ cell_idx)
{
    int bk = blockIdx.x, t = threadIdx.x;
    if (bk < FILLB) {
        GDC_WAIT();                 // needs g_cnt cursors from scan
        int r = bk / FSEG, seg = bk % FSEG;
        const int* dstp = ei + (r*2 + 1)*Ee + seg*FCHUNK;
        const int* srcp = ei + (r*2 + 0)*Ee + seg*FCHUNK;
        const float* wp = ew + r*Ee + seg*FCHUNK;
        for (int e = t; e < FCHUNK; e += 256) {
            int dst = dstp[e];
            int pos = atomicAdd(&g_cnt[r*Nn + dst], 1);
            float wv = wp[e];
            __half2 wh = __floats2half2_rn(wv, wv);
            g_epk[r*Ee + pos] = make_int2(srcp[e], *(int*)&wh);
        }
        GDC_LAUNCH();
        return;
    }
    // ---- init x: reads only g_film (transitively complete) + inputs ----
    __shared__ float sp[1664];
    for (int i = t; i < 1664; i += 256) {
        float v;
        if (i < 64)        v = W_se[i];
        else if (i < 128)  v = b_se[i - 64];
        else if (i < 640) {
            int j = i - 128, b = j >> 6, h = j & 63;
            v = cell_emb[cell_idx[b]*Hh + h];
        } else if (i < 1152) {
            int j = i - 640, b = j >> 6, h = j & 63;
            v = g_film[b*128 + h];
        } else {
            int j = i - 1152, b = j >> 6, h = j & 63;
            v = g_film[b*128 + 64 + h];
        }
        sp[i] = v;
    }
    __syncthreads();

    int i = (bk - FILLB)*256 + t;
    if (i < ROWS*8) {
        int q = i & 7;
        int m = i >> 3;
        int b = m & 7;
        int n = m >> 3;
        float v1 = ctl[b*Nn + n], v2 = drug[b*Nn + n];
        const float4* w4  = (const float4*)&sp[q*8];
        const float4* bb4 = (const float4*)&sp[64 + q*8];
        const float4* ce4 = (const float4*)&sp[128 + b*64 + q*8];
        const float4* g4  = (const float4*)&sp[640 + b*64 + q*8];
        const float4* be4 = (const float4*)&sp[1152 + b*64 + q*8];
        uint4 outv;
        unsigned* op = (unsigned*)&outv;
        #pragma unroll
        for (int p = 0; p < 2; p++) {
            float4 w = w4[p], bb = bb4[p], ce = ce4[p], gg = g4[p], be = be4[p];
            float o[4];
            o[0] = fmaf(fmaxf(fmaf(v1, w.x, bb.x), 0.f) + fmaxf(fmaf(v2, w.x, bb.x), 0.f) + ce.x, gg.x, be.x);
            o[1] = fmaf(fmaxf(fmaf(v1, w.y, bb.y), 0.f) + fmaxf(fmaf(v2, w.y, bb.y), 0.f) + ce.y, gg.y, be.y);
            o[2] = fmaf(fmaxf(fmaf(v1, w.z, bb.z), 0.f) + fmaxf(fmaf(v2, w.z, bb.z), 0.f) + ce.z, gg.z, be.z);
            o[3] = fmaf(fmaxf(fmaf(v1, w.w, bb.w), 0.f) + fmaxf(fmaf(v2, w.w, bb.w), 0.f) + ce.w, gg.w, be.w);
            __half2 h0 = __floats2half2_rn(o[0], o[1]);
            __half2 h1 = __floats2half2_rn(o[2], o[3]);
            op[p*2]   = *(unsigned*)&h0;
            op[p*2+1] = *(unsigned*)&h1;
        }
        ((uint4*)g_xh)[i] = outv;
    }
    GDC_LAUNCH();
}

// ---------------- gather: per-dst block, loops r; HFMA2 windows -------------
__device__ __forceinline__ void hacc4(__half2* a, uint4 v, __half2 w2)
{
    a[0] = __hfma2(*(__half2*)&v.x, w2, a[0]);
    a[1] = __hfma2(*(__half2*)&v.y, w2, a[1]);
    a[2] = __hfma2(*(__half2*)&v.z, w2, a[2]);
    a[3] = __hfma2(*(__half2*)&v.w, w2, a[3]);
}
__device__ __forceinline__ void hflush(float* f, __half2* a, __half2 hz)
{
    #pragma unroll
    for (int q = 0; q < 4; q++) {
        float2 x = __half22float2(a[q]);
        f[2*q]   += x.x;
        f[2*q+1] += x.y;
        a[q] = hz;
    }
}

__global__ __launch_bounds__(64)
void gather_kernel()  // grid (Nn) x 64; loops r internally
{
    __shared__ int2 sM[GCH];
    int dst = blockIdx.x;
    int t = threadIdx.x;                       // owns 8 halfs of the 512-half row
    // rowptr from scan (>=2 kernels back; transitively complete) -> pre-wait
    int st[Rr], en[Rr];
    #pragma unroll
    for (int r = 0; r < Rr; r++) {
        st[r] = g_rowptr[r*(Nn+1) + dst];
        en[r] = g_rowptr[r*(Nn+1) + dst + 1];
    }
    GDC_WAIT();                                // x / meta from predecessor
    const uint4* __restrict__ xq = (const uint4*)g_xh;   // 64 uint4 per node row
    const __half2 hz = __float2half2_rn(0.f);

    #pragma unroll
    for (int r = 0; r < Rr; r++) {
        const int2* __restrict__ ep = g_epk + r*Ee;
        float accf[8] = {0.f, 0.f, 0.f, 0.f, 0.f, 0.f, 0.f, 0.f};
        for (int base = st[r]; base < en[r]; base += GCH) {
            int n = min(GCH, en[r] - base);
            if (t < n)       sM[t]      = ep[base + t];
            if (t + 64 < n)  sM[t + 64] = ep[base + t + 64];
            __syncthreads();
            int j = 0;
            for (; j + 8 <= n; j += 8) {
                __half2 a[4] = {hz, hz, hz, hz};
                int2 m0 = sM[j],   m1 = sM[j+1], m2 = sM[j+2], m3 = sM[j+3];
                int2 m4 = sM[j+4], m5 = sM[j+5], m6 = sM[j+6], m7 = sM[j+7];
                uint4 v0 = xq[m0.x*64 + t];
                uint4 v1 = xq[m1.x*64 + t];
                uint4 v2 = xq[m2.x*64 + t];
                uint4 v3 = xq[m3.x*64 + t];
                uint4 v4 = xq[m4.x*64 + t];
                uint4 v5 = xq[m5.x*64 + t];
                uint4 v6 = xq[m6.x*64 + t];
                uint4 v7 = xq[m7.x*64 + t];
                hacc4(a, v0, *(__half2*)&m0.y);
                hacc4(a, v1, *(__half2*)&m1.y);
                hacc4(a, v2, *(__half2*)&m2.y);
                hacc4(a, v3, *(__half2*)&m3.y);
                hacc4(a, v4, *(__half2*)&m4.y);
                hacc4(a, v5, *(__half2*)&m5.y);
                hacc4(a, v6, *(__half2*)&m6.y);
                hacc4(a, v7, *(__half2*)&m7.y);
                hflush(accf, a, hz);
            }
            if (j < n) {
                __half2 a[4] = {hz, hz, hz, hz};
                for (; j < n; j++) {
                    int2 m0 = sM[j];
                    uint4 v0 = xq[m0.x*64 + t];
                    hacc4(a, v0, *(__half2*)&m0.y);
                }
                hflush(accf, a, hz);
            }
            __syncthreads();
        }
        uint4 hw;
        unsigned* hp = (unsigned*)&hw;
        #pragma unroll
        for (int q = 0; q < 4; q++) {
            __half2 h = __floats2half2_rn(accf[2*q], accf[2*q+1]);
            hp[q] = *(unsigned*)&h;
        }
        ((uint4*)(g_aggh + r*(ROWS*Hh) + dst*512))[t] = hw;
    }
    GDC_LAUNCH();
}

// ---------------- HMMA GEMM (double-buffered staging) + LN + ReLU -----------
__global__ __launch_bounds__(256)
void gemm_mma_kernel(const float* __restrict__ ln_g, const float* __restrict__ ln_b,
                     const float* __restrict__ W_out, const float* __restrict__ b_out,
                     float* __restrict__ out, int layer, int final_layer)
{
    __shared__ __half sA[2][128][72];
    __shared__ uint2  sBs[2][1024];
    __shared__ float  sLN[194];

    int tid = threadIdx.x;
    int wid = tid >> 5, lane = tid & 31;
    int qr = lane >> 2, qc = lane & 3;

    // LN/out params are kernel inputs -> stage before the dependency wait
    if (tid < 64)        sLN[tid] = ln_g[layer*64 + tid];
    else if (tid < 128)  sLN[tid] = ln_b[layer*64 + tid - 64];
    else if (tid < 192)  sLN[tid] = W_out[tid - 128];
    else if (tid == 192) sLN[192] = b_out[0];
    GDC_WAIT();                                // agg/x from gather

    int m0 = blockIdx.x*128;
    int rl = wid*16 + qr;

    float c[8][4];
    #pragma unroll
    for (int nt = 0; nt < 8; nt++)
        #pragma unroll
        for (int i = 0; i < 4; i++) c[nt][i] = 0.f;

    // staging helper
    auto stage = [&](int s, int buf) {
        const uint4* Asrc = (const uint4*)(((s == 0) ? g_xh
                                : (g_aggh + (s-1)*(ROWS*Hh))) + m0*64);
        #pragma unroll
        for (int i = tid; i < 1024; i += 256) {
            int row = i >> 3, cq = i & 7;
            *(uint4*)&sA[buf][row][cq*8] = Asrc[i];
        }
        const uint4* bsrc = (const uint4*)(g_bfrag + layer*4096 + s*1024);
        #pragma unroll
        for (int i = tid; i < 512; i += 256) ((uint4*)sBs[buf])[i] = bsrc[i];
    };

    stage(0, 0);
    #pragma unroll
    for (int s = 0; s < 4; s++) {
        int buf = s & 1;
        __syncthreads();                       // buf[s] ready; buf[s^1] free
        if (s < 3) stage(s + 1, buf ^ 1);      // prefetch next stream
        #pragma unroll
        for (int kti = 0; kti < 4; kti++) {
            int kh = kti*16 + qc*2;
            uint32_t a0 = *(const uint32_t*)&sA[buf][rl][kh];
            uint32_t a1 = *(const uint32_t*)&sA[buf][rl + 8][kh];
            uint32_t a2 = *(const uint32_t*)&sA[buf][rl][kh + 8];
            uint32_t a3 = *(const uint32_t*)&sA[buf][rl + 8][kh + 8];
            #pragma unroll
            for (int nt = 0; nt < 8; nt++) {
                uint2 b = sBs[buf][(kti*8 + nt)*32 + lane];
                asm volatile(
                    "mma.sync.aligned.m16n8k16.row.col.f32.f16.f16.f32 "
                    "{%0,%1,%2,%3}, {%4,%5,%6,%7}, {%8,%9}, {%0,%1,%2,%3};"
                    : "+f"(c[nt][0]), "+f"(c[nt][1]), "+f"(c[nt][2]), "+f"(c[nt][3])
                    : "r"(a0), "r"(a1), "r"(a2), "r"(a3), "r"(b.x), "r"(b.y));
            }
        }
    }

    #pragma unroll
    for (int h = 0; h < 2; h++) {
        int row = m0 + rl + h*8;
        float sum = 0.f, sq = 0.f;
        #pragma unroll
        for (int nt = 0; nt < 8; nt++) {
            float v0 = c[nt][2*h], v1 = c[nt][2*h + 1];
            sum += v0 + v1;
            sq   = fmaf(v0, v0, fmaf(v1, v1, sq));
        }
        sum += __shfl_xor_sync(0xffffffffu, sum, 1);
        sq  += __shfl_xor_sync(0xffffffffu, sq, 1);
        sum += __shfl_xor_sync(0xffffffffu, sum, 2);
        sq  += __shfl_xor_sync(0xffffffffu, sq, 2);
        float mu  = sum * (1.f/64.f);
        float var = sq  * (1.f/64.f) - mu*mu;
        float inv = rsqrtf(var + LN_EPS);
        if (!final_layer) {
            #pragma unroll
            for (int nt = 0; nt < 8; nt++) {
                int col = nt*8 + qc*2;
                float o0 = fmaxf(fmaf((c[nt][2*h]  -mu)*inv, sLN[col],   sLN[64+col]),   0.f);
                float o1 = fmaxf(fmaf((c[nt][2*h+1]-mu)*inv, sLN[col+1], sLN[64+col+1]), 0.f);
                __half2 hv = __floats2half2_rn(o0, o1);
                *(unsigned*)(g_xh + row*64 + col) = *(unsigned*)&hv;
            }
        } else {
            float dot = 0.f;
            #pragma unroll
            for (int nt = 0; nt < 8; nt++) {
                int col = nt*8 + qc*2;
                float o0 = fmaxf(fmaf((c[nt][2*h]  -mu)*inv, sLN[col],   sLN[64+col]),   0.f);
                float o1 = fmaxf(fmaf((c[nt][2*h+1]-mu)*inv, sLN[col+1], sLN[64+col+1]), 0.f);
                dot = fmaf(o0, sLN[128+col], fmaf(o1, sLN[128+col+1], dot));
            }
            dot += __shfl_xor_sync(0xffffffffu, dot, 1);
            dot += __shfl_xor_sync(0xffffffffu, dot, 2);
            if (qc == 0) {
                int b = row & 7, n = row >> 3;
                out[b*Nn + n] = dot + sLN[192];
            }
        }
    }
    GDC_LAUNCH();
}

// ---------------- PDL launch helper ----------------
static void launch_pdl(const void* fn, dim3 grid, dim3 block, void** args)
{
    cudaLaunchConfig_t cfg = {};
    cfg.gridDim = grid;
    cfg.blockDim = block;
    cfg.dynamicSmemBytes = 0;
    cfg.stream = 0;
    cudaLaunchAttribute at[1];
    at[0].id = cudaLaunchAttributeProgrammaticStreamSerialization;
    at[0].val.programmaticStreamSerializationAllowed = 1;
    cfg.attrs = at;
    cfg.numAttrs = 1;
    cudaLaunchKernelExC(&cfg, fn, args);
}

// ---------------- launch ----------------
extern "C" void kernel_launch(void* const* d_in, const int* in_sizes, int n_in,
                              void* d_out, int out_size)
{
    const float* ctl      = (const float*)d_in[0];
    const float* drug     = (const float*)d_in[1];
    const float* fp       = (const float*)d_in[2];
    const float* ew       = (const float*)d_in[3];
    const int*   cell_idx = (const int*)  d_in[4];
    const int*   ei       = (const int*)  d_in[5];
    const float* W_se     = (const float*)d_in[6];
    const float* b_se     = (const float*)d_in[7];
    const float* cell_emb = (const float*)d_in[8];
    const float* W_f1     = (const float*)d_in[9];
    const float* b_f1     = (const float*)d_in[10];
    const float* W_f2     = (const float*)d_in[11];
    const float* b_f2     = (const float*)d_in[12];
    const float* Wself    = (const float*)d_in[13];
    const float* Wrel     = (const float*)d_in[14];
    const float* ln_g     = (const float*)d_in[15];
    const float* ln_b     = (const float*)d_in[16];
    const float* W_out    = (const float*)d_in[17];
    const float* b_out    = (const float*)d_in[18];
    float* out = (float*)d_out;

    int npre = FILLB + Bn + (Ll*16*8*32 + 1023)/1024;   // 216
    {
        void* a[] = {(void*)&ei, (void*)&fp, (void*)&W_f1, (void*)&b_f1,
                     (void*)&W_f2, (void*)&b_f2, (void*)&Wself, (void*)&Wrel};
        launch_pdl((const void*)pre_kernel, dim3(npre), dim3(1024), a);      // 1
    }
    {
        void* a[] = {nullptr};
        launch_pdl((const void*)scan_kernel, dim3(Rr), dim3(1024), a);       // 2
    }
    {
        void* a[] = {(void*)&ei, (void*)&ew, (void*)&ctl, (void*)&drug,
                     (void*)&W_se, (void*)&b_se, (void*)&cell_emb, (void*)&cell_idx};
        launch_pdl((const void*)fillinit_kernel,
                   dim3(FILLB + (ROWS*8 + 255)/256), dim3(256), a);          // 3
    }

    int layers[Ll]  = {0, 1, 2, 3};
    int finals[Ll]  = {0, 0, 0, 1};
    for (int l = 0; l < Ll; l++) {
        {
            void* a[] = {nullptr};
            launch_pdl((const void*)gather_kernel, dim3(Nn), dim3(64), a);
        }
        {
            void* a[] = {(void*)&ln_g, (void*)&ln_b, (void*)&W_out, (void*)&b_out,
                         (void*)&out, (void*)&layers[l], (void*)&finals[l]};
            launch_pdl((const void*)gemm_mma_kernel, dim3(ROWS/128), dim3(256), a);
        }
    }
}